// round 5
// baseline (speedup 1.0000x reference)
#include <cuda_runtime.h>
#include <cstdint>

#define B_   512
#define F_   512
#define NK   50
#define DK   16
#define NCOL (NK * DK)     // 800
#define OUTW (F_ + NK)     // 562

// act in [k][b][d] layout
__device__ float g_act[B_ * NCOL];

// ---------------------------------------------------------------------------
// Kernel 1: tf32 tensor-core GEMM  act[b, n] = sum_k x[b,k] * W[k,n]
// CTA tile 64(M) x 64(N) x 32(K-slab), 256 threads = 8 warps (4x2),
// warp tile 16x32 = 1(m16) x 4(n8) mma.sync.m16n8k8 tiles.
// Prologue initializes out[:, :512] = x and out[:, 512:] = 0.
// ---------------------------------------------------------------------------
__global__ __launch_bounds__(256) void gemm_kernel(const float* __restrict__ x,
                                                   const float* __restrict__ Wm,
                                                   float* __restrict__ out) {
    // ---- fused init of the output buffer (grid-stride) ----
    {
        int gtid = (blockIdx.y * 13 + blockIdx.x) * 256 + threadIdx.x;
        const int nthreads = 13 * 8 * 256;
        for (int i = gtid; i < B_ * OUTW; i += nthreads) {
            int b = i / OUTW;
            int j = i - b * OUTW;
            out[i] = (j < F_) ? x[b * F_ + j] : 0.0f;
        }
    }

    __shared__ float As[32][72];   // [k][cm] permuted-m columns, stride 72 (==8 mod 32)
    __shared__ float Bs[32][72];   // [k][n],  stride 72

    const int tid  = threadIdx.x;
    const int warp = tid >> 5;
    const int lane = tid & 31;
    const int gid  = lane >> 2;    // 0..7
    const int tig  = lane & 3;     // 0..3
    const int wm   = warp & 3;     // 4 warp-rows of 16
    const int wn   = warp >> 2;    // 2 warp-cols of 32

    const int n0 = blockIdx.x * 64;
    const int m0 = blockIdx.y * 64;

    // staging maps: 512 float4 per tile, 2 per thread
    // A: idx -> (row = idx>>3, k0 = (idx&7)*4);  B: idx -> (kk = idx>>4, c0 = (idx&15)*4)
    int a_row[2], a_k0[2], a_cm[2], b_kk[2], b_c0[2];
#pragma unroll
    for (int i = 0; i < 2; i++) {
        int idx = tid * 2 + i;
        a_row[i] = idx >> 3;
        a_k0[i]  = (idx & 7) << 2;
        int mt = a_row[i] >> 4, r = a_row[i] & 15;
        a_cm[i] = (mt << 4) + ((r & 7) << 1) + (r >> 3);   // paired-row perm
        b_kk[i] = idx >> 4;
        b_c0[i] = (idx & 15) << 2;
    }

    float acc[4][4];
#pragma unroll
    for (int nt = 0; nt < 4; nt++)
#pragma unroll
        for (int j = 0; j < 4; j++) acc[nt][j] = 0.0f;

    float4 pa[2], pb[2];

    // prefetch slab 0
#pragma unroll
    for (int i = 0; i < 2; i++) {
        pa[i] = *(const float4*)&x[(m0 + a_row[i]) * F_ + a_k0[i]];
        int c = n0 + b_c0[i];
        pb[i] = (c < NCOL) ? *(const float4*)&Wm[b_kk[i] * NCOL + c]
                           : make_float4(0.f, 0.f, 0.f, 0.f);
    }

    for (int s = 0; s < 16; s++) {
        // commit prefetched slab to SMEM
#pragma unroll
        for (int i = 0; i < 2; i++) {
            As[a_k0[i] + 0][a_cm[i]] = pa[i].x;
            As[a_k0[i] + 1][a_cm[i]] = pa[i].y;
            As[a_k0[i] + 2][a_cm[i]] = pa[i].z;
            As[a_k0[i] + 3][a_cm[i]] = pa[i].w;
            *(float4*)&Bs[b_kk[i]][b_c0[i]] = pb[i];
        }
        __syncthreads();

        // prefetch next slab while computing this one
        if (s < 15) {
            const int k0 = (s + 1) * 32;
#pragma unroll
            for (int i = 0; i < 2; i++) {
                pa[i] = *(const float4*)&x[(m0 + a_row[i]) * F_ + k0 + a_k0[i]];
                int c = n0 + b_c0[i];
                pb[i] = (c < NCOL) ? *(const float4*)&Wm[(k0 + b_kk[i]) * NCOL + c]
                                   : make_float4(0.f, 0.f, 0.f, 0.f);
            }
        }

#pragma unroll
        for (int ks = 0; ks < 4; ks++) {
            const int kr = ks * 8 + tig;
            // A fragment: paired-row layout -> two LDS.64
            uint32_t afr[4];
            {
                const int col = (wm << 4) + (gid << 1);
                float2 p01 = *(const float2*)&As[kr][col];
                float2 p23 = *(const float2*)&As[kr + 4][col];
                afr[0] = __float_as_uint(p01.x);
                afr[1] = __float_as_uint(p01.y);
                afr[2] = __float_as_uint(p23.x);
                afr[3] = __float_as_uint(p23.y);
            }
            uint32_t bfr[4][2];
#pragma unroll
            for (int nt = 0; nt < 4; nt++) {
                const int col = wn * 32 + nt * 8 + gid;
                bfr[nt][0] = __float_as_uint(Bs[kr][col]);
                bfr[nt][1] = __float_as_uint(Bs[kr + 4][col]);
            }
#pragma unroll
            for (int nt = 0; nt < 4; nt++) {
                asm volatile(
                    "mma.sync.aligned.m16n8k8.row.col.f32.tf32.tf32.f32 "
                    "{%0,%1,%2,%3}, {%4,%5,%6,%7}, {%8,%9}, {%0,%1,%2,%3};"
                    : "+f"(acc[nt][0]), "+f"(acc[nt][1]),
                      "+f"(acc[nt][2]), "+f"(acc[nt][3])
                    : "r"(afr[0]), "r"(afr[1]), "r"(afr[2]), "r"(afr[3]),
                      "r"(bfr[nt][0]), "r"(bfr[nt][1]));
            }
        }
        __syncthreads();
    }

    // epilogue: store transposed into g_act[k][b][d]
    {
        const int br = m0 + wm * 16 + gid;
#pragma unroll
        for (int nt = 0; nt < 4; nt++) {
            const int n = n0 + wn * 32 + nt * 8 + 2 * tig;
            if (n < NCOL) {
                const int kk = n >> 4;
                const int d  = n & 15;
                *(float2*)&g_act[kk * (B_ * DK) + br * DK + d] =
                    make_float2(acc[nt][0], acc[nt][1]);
                *(float2*)&g_act[kk * (B_ * DK) + (br + 8) * DK + d] =
                    make_float2(acc[nt][2], acc[nt][3]);
            }
        }
    }
}

// ---------------------------------------------------------------------------
// Kernel 2: pairwise L1 + exp, packed f32x2 math.
// grid = (NK, 4 b-chunks of 128, 4 b2-quarters of 128), 128 threads.
// 800 CTAs -> ~5.4 CTAs/SM -> ~5.4 warps/SMSP (latency hiding for the
// dependent f2add tree; R4 profile showed issue=54% at 2.7 warps/SMSP).
// ---------------------------------------------------------------------------
__device__ __forceinline__ unsigned long long f2add(unsigned long long a,
                                                    unsigned long long b) {
    unsigned long long r;
    asm("add.rn.f32x2 %0, %1, %2;" : "=l"(r) : "l"(a), "l"(b));
    return r;
}

__global__ __launch_bounds__(128) void pairwise_kernel(float* __restrict__ out) {
    const int k     = blockIdx.x;   // 0..49
    const int chunk = blockIdx.y;   // 0..3
    const int quart = blockIdx.z;   // 0..3

    __shared__ float sbuf[128 * DK];   // 8 KB

    const float* __restrict__ base = g_act + k * (B_ * DK);
    const int b2base = quart * 128;

    // Stage 128 rows into SMEM
    {
        const float4* s4 = (const float4*)(base + b2base * DK);
        float4* d4 = (float4*)sbuf;
#pragma unroll
        for (int i = threadIdx.x; i < 128 * DK / 4; i += 128) d4[i] = s4[i];
    }

    // Own row, negated and packed into 8 u64 (f32x2 lanes {lo=2j, hi=2j+1})
    const int b = chunk * 128 + threadIdx.x;
    unsigned long long an[8];
    {
        const float* a0 = base + b * DK;
#pragma unroll
        for (int j = 0; j < 8; j++) {
            unsigned long long p =
                ((unsigned long long)__float_as_uint(a0[2 * j + 1]) << 32)
                | (unsigned long long)__float_as_uint(a0[2 * j]);
            an[j] = p ^ 0x8000000080000000ull;   // negate both lanes
        }
    }
    __syncthreads();

    const unsigned long long MASK = 0x7fffffff7fffffffull;
    float fsum = 0.0f;

#pragma unroll 4
    for (int b2 = 0; b2 < 128; b2++) {
        const ulonglong2* sp = ((const ulonglong2*)sbuf) + (b2 << 2);
        ulonglong2 q0 = sp[0];   // broadcast LDS.128, conflict-free
        ulonglong2 q1 = sp[1];
        ulonglong2 q2 = sp[2];
        ulonglong2 q3 = sp[3];

        unsigned long long m0 = f2add(q0.x, an[0]) & MASK;
        unsigned long long m1 = f2add(q0.y, an[1]) & MASK;
        unsigned long long m2 = f2add(q1.x, an[2]) & MASK;
        unsigned long long m3 = f2add(q1.y, an[3]) & MASK;
        unsigned long long m4 = f2add(q2.x, an[4]) & MASK;
        unsigned long long m5 = f2add(q2.y, an[5]) & MASK;
        unsigned long long m6 = f2add(q3.x, an[6]) & MASK;
        unsigned long long m7 = f2add(q3.y, an[7]) & MASK;

        unsigned long long t0 = f2add(m0, m1);
        unsigned long long t1 = f2add(m2, m3);
        unsigned long long t2 = f2add(m4, m5);
        unsigned long long t3 = f2add(m6, m7);
        t0 = f2add(t0, t1);
        t2 = f2add(t2, t3);
        t0 = f2add(t0, t2);

        float lo = __uint_as_float((unsigned int)t0);
        float hi = __uint_as_float((unsigned int)(t0 >> 32));
        float l1 = lo + hi;

        fsum += __expf(-l1);
    }

    atomicAdd(&out[b * OUTW + F_ + k], fsum);
}

// ---------------------------------------------------------------------------
extern "C" void kernel_launch(void* const* d_in, const int* in_sizes, int n_in,
                              void* d_out, int out_size) {
    const float* x = (const float*)d_in[0];
    const float* W = (const float*)d_in[1];
    // Defensive: identify by element count (x = 512*512, W = 512*800)
    if (n_in >= 2 && in_sizes[0] == F_ * NCOL && in_sizes[1] == B_ * F_) {
        const float* t = x; x = W; W = t;
    }
    float* out = (float*)d_out;

    gemm_kernel<<<dim3(13, 8), 256>>>(x, W, out);
    pairwise_kernel<<<dim3(NK, 4, 4), 128>>>(out);
}